// round 1
// baseline (speedup 1.0000x reference)
#include <cuda_runtime.h>
#include <cstddef>

#define B_ 1024
#define E_ 8192
#define R_ 16
#define D_ 128
#define BT 64
#define ET 64
#define EBLK (E_/ET)   // 128

// Scratch (no allocation allowed)
__device__ float g_c[R_*E_];       // c[r,e] = zz[e] - 2*rz[r,e]
__device__ float g_g[E_];          // g[e]   = zz[e] + 2*zq[e]
__device__ float g_u[B_*R_];       // u[b,r] = hh[b] + rr[r] + 2*hr[b,r]
__device__ float g_v[B_];          // v[b]   = tt[b] + qq - 2*qt[b]
__device__ float g_part[EBLK*B_];  // partial sums per e-block

__device__ __forceinline__ float wsum(float v){
  v += __shfl_xor_sync(0xffffffffu, v, 16);
  v += __shfl_xor_sync(0xffffffffu, v, 8);
  v += __shfl_xor_sync(0xffffffffu, v, 4);
  v += __shfl_xor_sync(0xffffffffu, v, 2);
  v += __shfl_xor_sync(0xffffffffu, v, 1);
  return v;
}
__device__ __forceinline__ float dot4(float4 a, float4 b){
  return fmaf(a.x,b.x, fmaf(a.y,b.y, fmaf(a.z,b.z, a.w*b.w)));
}
__device__ __forceinline__ float sqrt_approx(float x){
  float y; asm("sqrt.approx.f32 %0, %1;" : "=f"(y) : "f"(x)); return y;
}

// ---------------- per-entity precompute: zz, g, c ----------------
__global__ void k_pre_e(const float* __restrict__ Etab,
                        const float* __restrict__ rules,
                        const int* __restrict__ qrelp){
  __shared__ __align__(16) float rs[R_*D_];
  int tid = threadIdx.x;
  for (int i = tid; i < R_*D_; i += blockDim.x) rs[i] = rules[i];
  __syncthreads();
  int qrel = *qrelp;
  int lane = tid & 31, warp = tid >> 5;
  int e = blockIdx.x*8 + warp;
  float4 zv = ((const float4*)(Etab + (size_t)e*D_))[lane];
  float zz = wsum(dot4(zv, zv));
  float4 qv = ((const float4*)(rs + qrel*D_))[lane];
  float zq = wsum(dot4(zv, qv));
  if (lane == 0) g_g[e] = zz + 2.f*zq;
  #pragma unroll
  for (int r = 0; r < R_; r++){
    float4 rv = ((const float4*)(rs + r*D_))[lane];
    float rz = wsum(dot4(zv, rv));
    if (lane == 0) g_c[r*E_ + e] = zz - 2.f*rz;
  }
}

// ---------------- per-batch precompute: u, v ----------------
__global__ void k_pre_b(const float* __restrict__ Etab,
                        const float* __restrict__ rules,
                        const int* __restrict__ head,
                        const int* __restrict__ tail,
                        const int* __restrict__ qrelp){
  __shared__ __align__(16) float rs[R_*D_];
  __shared__ float rr[R_];
  int tid = threadIdx.x;
  for (int i = tid; i < R_*D_; i += blockDim.x) rs[i] = rules[i];
  __syncthreads();
  if (tid < R_){
    float s = 0.f;
    for (int k = 0; k < D_; k++) s = fmaf(rs[tid*D_+k], rs[tid*D_+k], s);
    rr[tid] = s;
  }
  __syncthreads();
  int qrel = *qrelp;
  int lane = tid & 31, warp = tid >> 5;
  int b = blockIdx.x*8 + warp;
  float4 hv = ((const float4*)(Etab + (size_t)head[b]*D_))[lane];
  float4 tv = ((const float4*)(Etab + (size_t)tail[b]*D_))[lane];
  float hh = wsum(dot4(hv, hv));
  float tt = wsum(dot4(tv, tv));
  float4 qv = ((const float4*)(rs + qrel*D_))[lane];
  float tq = wsum(dot4(tv, qv));
  if (lane == 0) g_v[b] = tt + rr[qrel] - 2.f*tq;
  #pragma unroll
  for (int r = 0; r < R_; r++){
    float4 rv = ((const float4*)(rs + r*D_))[lane];
    float hr = wsum(dot4(hv, rv));
    if (lane == 0) g_u[b*R_ + r] = hh + rr[r] + 2.f*hr;
  }
}

// ---------------- main fused kernel ----------------
// smem floats: hs 8192, ts 8192, zs 8192 (k-major), cs 1024, us 1024,
//              gs 64, vs 64, hix/tix 128 ints
#define SMEM_FLOATS (8192*3 + 1024*2 + 64*2 + 128)

__global__ __launch_bounds__(256, 1) void k_main(const float* __restrict__ Etab,
                                                 const int* __restrict__ head,
                                                 const int* __restrict__ tail){
  extern __shared__ __align__(16) float sm[];
  float* hs = sm;               // [64][128] row-major
  float* ts = hs + 8192;        // [64][128]
  float* zs = ts + 8192;        // [128][64] k-major (transposed)
  float* cs = zs + 8192;        // [16][64]
  float* us = cs + 1024;        // [64][16]
  float* gs = us + 1024;        // [64]
  float* vs = gs + 64;          // [64]
  int*  hix = (int*)(vs + 64);  // [64]
  int*  tix = hix + 64;         // [64]

  int tid = threadIdx.x;
  int e0 = blockIdx.x * ET, b0 = blockIdx.y * BT;

  if (tid < 64){ hix[tid] = head[b0+tid]; tix[tid] = tail[b0+tid]; vs[tid] = g_v[b0+tid]; }
  else if (tid < 128){ gs[tid-64] = g_g[e0 + tid - 64]; }
  for (int i = tid; i < BT*R_; i += 256) us[i] = g_u[b0*R_ + i];
  for (int i = tid; i < R_*ET; i += 256){
    int r = i >> 6, e = i & 63;
    cs[i] = g_c[r*E_ + e0 + e];
  }
  __syncthreads();

  #pragma unroll
  for (int it = 0; it < 8; it++){
    int idx = it*256 + tid;
    int row = idx >> 5, col = idx & 31;          // coalesced h/t loads
    float4 a = __ldg((const float4*)(Etab + (size_t)hix[row]*D_) + col);
    *(float4*)(hs + row*128 + col*4) = a;
    float4 b = __ldg((const float4*)(Etab + (size_t)tix[row]*D_) + col);
    *(float4*)(ts + row*128 + col*4) = b;
    int ze = idx & 63, zc = idx >> 6;            // lane-per-e -> conflict-free k-major store
    float4 z = __ldg((const float4*)(Etab + (size_t)(e0+ze)*D_) + zc);
    zs[(zc*4+0)*64 + ze] = z.x;
    zs[(zc*4+1)*64 + ze] = z.y;
    zs[(zc*4+2)*64 + ze] = z.z;
    zs[(zc*4+3)*64 + ze] = z.w;
  }
  __syncthreads();

  int tx = tid & 15, ty = tid >> 4;
  const float* hp = hs + ty*4*128;
  const float* tp = ts + ty*4*128;
  const float* zp = zs + tx*4;

  float hz[4][4], zt[4][4];
  #pragma unroll
  for (int i = 0; i < 4; i++)
    #pragma unroll
    for (int j = 0; j < 4; j++){ hz[i][j] = 0.f; zt[i][j] = 0.f; }

  #pragma unroll 4
  for (int kk = 0; kk < 32; kk++){
    float hA[4][4], tA[4][4], zA[4][4];
    #pragma unroll
    for (int i = 0; i < 4; i++){
      float4 a = *(const float4*)(hp + i*128 + kk*4);
      hA[i][0]=a.x; hA[i][1]=a.y; hA[i][2]=a.z; hA[i][3]=a.w;
      float4 b = *(const float4*)(tp + i*128 + kk*4);
      tA[i][0]=b.x; tA[i][1]=b.y; tA[i][2]=b.z; tA[i][3]=b.w;
    }
    #pragma unroll
    for (int m = 0; m < 4; m++){
      float4 z = *(const float4*)(zp + (kk*4+m)*64);
      zA[m][0]=z.x; zA[m][1]=z.y; zA[m][2]=z.z; zA[m][3]=z.w;
    }
    #pragma unroll
    for (int m = 0; m < 4; m++)
      #pragma unroll
      for (int i = 0; i < 4; i++)
        #pragma unroll
        for (int j = 0; j < 4; j++){
          hz[i][j] = fmaf(hA[i][m], zA[m][j], hz[i][j]);
          zt[i][j] = fmaf(tA[i][m], zA[m][j], zt[i][j]);
        }
  }

  // epilogue: s2 then sum_r sqrt(sq1)
  float s2v[4][4];
  #pragma unroll
  for (int i = 0; i < 4; i++){
    float vb = vs[ty*4+i];
    #pragma unroll
    for (int j = 0; j < 4; j++){
      float sq2 = fmaf(-2.f, zt[i][j], vb + gs[tx*4+j]);
      s2v[i][j] = sqrt_approx(fmaxf(sq2, 0.f));
    }
  }
  float S1[4][4];
  #pragma unroll
  for (int i = 0; i < 4; i++)
    #pragma unroll
    for (int j = 0; j < 4; j++) S1[i][j] = 0.f;

  #pragma unroll
  for (int r = 0; r < R_; r++){
    float ur[4], cr[4];
    #pragma unroll
    for (int i = 0; i < 4; i++) ur[i] = us[(ty*4+i)*R_ + r];
    #pragma unroll
    for (int j = 0; j < 4; j++) cr[j] = cs[r*64 + tx*4 + j];
    #pragma unroll
    for (int i = 0; i < 4; i++)
      #pragma unroll
      for (int j = 0; j < 4; j++){
        float x = fmaf(-2.f, hz[i][j], ur[i] + cr[j]);
        S1[i][j] += sqrt_approx(fmaxf(x, 0.f));
      }
  }

  float res[4];
  #pragma unroll
  for (int i = 0; i < 4; i++){
    float s = 0.f;
    #pragma unroll
    for (int j = 0; j < 4; j++) s = fmaf(S1[i][j], s2v[i][j], s);
    res[i] = s;
  }

  __syncthreads();
  #pragma unroll
  for (int i = 0; i < 4; i++) hs[(ty*4+i)*16 + tx] = res[i];
  __syncthreads();
  if (tid < 64){
    float s = 0.f;
    #pragma unroll
    for (int x = 0; x < 16; x++) s += hs[tid*16 + x];
    g_part[blockIdx.x*B_ + b0 + tid] = s;
  }
}

// ---------------- final deterministic reduction ----------------
__global__ void k_final(float* __restrict__ out){
  int b = blockIdx.x*256 + threadIdx.x;
  float s = 0.f;
  #pragma unroll 8
  for (int e = 0; e < EBLK; e++) s += g_part[e*B_ + b];
  out[b] = s * (1.f/(float)E_);
}

extern "C" void kernel_launch(void* const* d_in, const int* in_sizes, int n_in,
                              void* d_out, int out_size){
  const int*   head  = (const int*)d_in[0];
  const int*   tail  = (const int*)d_in[1];
  const int*   qrel  = (const int*)d_in[2];
  // d_in[3] = depth (fixed at 1, unused)
  const float* Etab  = (const float*)d_in[4];
  const float* rules = (const float*)d_in[5];
  float* out = (float*)d_out;

  size_t smem = (size_t)SMEM_FLOATS * sizeof(float);
  cudaFuncSetAttribute(k_main, cudaFuncAttributeMaxDynamicSharedMemorySize, (int)smem);

  k_pre_e<<<E_/8, 256>>>(Etab, rules, qrel);
  k_pre_b<<<B_/8, 256>>>(Etab, rules, head, tail, qrel);
  dim3 grid(E_/ET, B_/BT);
  k_main<<<grid, 256, smem>>>(Etab, head, tail);
  k_final<<<B_/256, 256>>>(out);
}